// round 13
// baseline (speedup 1.0000x reference)
#include <cuda_runtime.h>
#include <math.h>

#define BB 8
#define SS 4096
#define HH 4096
#define DD 128
#define NMAX 64
#define HC 4              // h chunks
#define HCH (HH/HC)       // 1024
#define RT 8              // rows per tile
#define NT 9              // 8 k/v row tiles + 1 q tile

// ---- scratch (no allocations allowed) ----
__device__ int   g_pos[BB][NMAX];
__device__ int   g_cnt[BB];
__device__ float g_pk[BB][NMAX+1][HC][DD];   // partial k (slots 0..63) / q (slot 64)
__device__ float g_pv[BB][NMAX][HC];         // partial v
__device__ float g_k[BB][NMAX][DD];
__device__ float g_v[BB][NMAX];
__device__ float g_q[BB][DD];

// Kernel 1: sentence positions via per-warp ballot two-pass. 4 warps x 1024 positions.
__global__ void k_prep(const int* __restrict__ mask) {
    int b = blockIdx.x;
    int t = threadIdx.x, w = t >> 5, lane = t & 31;
    const int* mrow = mask + b * SS;
    __shared__ int wcnt[4];
    int cnt = 0;
    for (int it = 0; it < 32; it++) {
        int p = w * 1024 + it * 32 + lane;
        unsigned bal = __ballot_sync(0xffffffffu, mrow[p] > 0);
        cnt += __popc(bal);
    }
    if (lane == 0) wcnt[w] = cnt;
    __syncthreads();
    int base = 0;
    for (int i = 0; i < w; i++) base += wcnt[i];
    int run = base;
    unsigned lmask = (1u << lane) - 1u;
    for (int it = 0; it < 32; it++) {
        int p = w * 1024 + it * 32 + lane;
        bool s = mrow[p] > 0;
        unsigned bal = __ballot_sync(0xffffffffu, s);
        if (s) {
            int r = run + __popc(bal & lmask);
            if (r < NMAX) g_pos[b][r] = p;
        }
        run += __popc(bal);
    }
    if (t == 0) {
        int tot = wcnt[0] + wcnt[1] + wcnt[2] + wcnt[3];
        g_cnt[b] = tot < NMAX ? tot : NMAX;
    }
}

// Kernel 2: gathered GEMV. grid (HC, NT, B). Each block: 8 rows x 1024-h chunk.
// Warp w owns row w: 32 lanes x 4 d = 128 output dims, loop over 1024 h.
__global__ void __launch_bounds__(256) k_gemv(const float* __restrict__ hs,
                                              const float* __restrict__ Wq,
                                              const float* __restrict__ Wk,
                                              const float* __restrict__ Wr) {
    int hc = blockIdx.x, tile = blockIdx.y, b = blockIdx.z;
    int t = threadIdx.x, w = t >> 5, lane = t & 31;
    int cnt = g_cnt[b];
    bool qtile = (tile == NT - 1);
    if (!qtile && tile * RT >= cnt) return;   // uniform block-wide exit

    __shared__ __align__(16) float sh[RT][HCH];  // 32 KB
    const float4* hs4 = (const float4*)hs;
    for (int r = 0; r < RT; r++) {
        int slot = tile * RT + r;
        bool valid = qtile ? (r == 0) : (slot < cnt);
        if (!valid) continue;                 // uniform per r
        int pos = qtile ? g_pos[b][cnt - 1] : g_pos[b][slot];
        const float4* src = hs4 + ((size_t)(b * SS + pos) * HH + (size_t)hc * HCH) / 4;
        ((float4*)sh[r])[t] = src[t];         // 256 thr * 4 floats = 1024 floats
    }
    __syncthreads();

    int slot = tile * RT + w;
    bool valid = qtile ? (w == 0) : (slot < cnt);
    if (!valid) return;

    const float* Wm = qtile ? Wq : Wk;
    const float4* W = (const float4*)Wm + (size_t)hc * HCH * (DD / 4) + lane;
    const float* hr = sh[w];
    float4 acc = make_float4(0.f, 0.f, 0.f, 0.f);
#pragma unroll 8
    for (int h = 0; h < HCH; h++) {
        float hv = hr[h];
        float4 wv = W[(size_t)h * (DD / 4)];
        acc.x = fmaf(hv, wv.x, acc.x);
        acc.y = fmaf(hv, wv.y, acc.y);
        acc.z = fmaf(hv, wv.z, acc.z);
        acc.w = fmaf(hv, wv.w, acc.w);
    }
    int outslot = qtile ? NMAX : slot;
    ((float4*)g_pk[b][outslot][hc])[lane] = acc;

    if (!qtile) {
        float va = 0.f;
        const float* wr = Wr + hc * HCH;
        for (int h = lane; h < HCH; h += 32) va = fmaf(hr[h], wr[h], va);
        for (int o = 16; o; o >>= 1) va += __shfl_xor_sync(0xffffffffu, va, o);
        if (lane == 0) g_pv[b][slot][hc] = va;
    }
}

// Kernel 3: reduce h-chunk partials, add bias, apply RoPE. grid (NMAX+1, B), 64 thr.
__global__ void k_rope(const float* __restrict__ bq, const float* __restrict__ bk,
                       const float* __restrict__ br) {
    int b = blockIdx.y, slot = blockIdx.x;   // 0..64
    int cnt = g_cnt[b];
    bool qs = (slot == NMAX);
    if (!qs && slot >= cnt) return;
    int t = threadIdx.x;                     // pair index 0..63
    int n = qs ? (cnt - 1) : slot;
    float a = 0.f, bv = 0.f;
#pragma unroll
    for (int c = 0; c < HC; c++) { a += g_pk[b][slot][c][2 * t]; bv += g_pk[b][slot][c][2 * t + 1]; }
    const float* bias = qs ? bq : bk;
    a += bias[2 * t]; bv += bias[2 * t + 1];
    float freq = expf(-(float)t * (9.210340371976184f / 64.0f));  // 10000^(-t/64)
    float ang = (float)n * freq;
    float sn, cs;
    sincosf(ang, &sn, &cs);                  // FIXED: sin pointer FIRST, cos second
    float ra = a * cs - bv * sn;
    float rb = a * sn + bv * cs;
    if (qs) { g_q[b][2 * t] = ra; g_q[b][2 * t + 1] = rb; }
    else {
        g_k[b][slot][2 * t] = ra; g_k[b][slot][2 * t + 1] = rb;
        if (t == 0) {
            float v = br[0];
#pragma unroll
            for (int c = 0; c < HC; c++) v += g_pv[b][slot][c];
            g_v[b][slot] = v;
        }
    }
}

// Kernel 4: attention softmax + rewards + pairwise loss. 1 block, warp b = batch b.
__global__ void k_attn(float* __restrict__ out, int out_size) {
    __shared__ float rew[BB];
    int t = threadIdx.x, b = t >> 5, lane = t & 31;
    int cnt = g_cnt[b];
    const float scale = 0.08838834764831845f; // 1/sqrt(128)
    int n0 = lane, n1 = lane + 32;
    float l0 = -INFINITY, l1 = -INFINITY;
    if (n0 < cnt) { float s = 0.f; for (int d = 0; d < DD; d++) s = fmaf(g_q[b][d], g_k[b][n0][d], s); l0 = s * scale; }
    if (n1 < cnt) { float s = 0.f; for (int d = 0; d < DD; d++) s = fmaf(g_q[b][d], g_k[b][n1][d], s); l1 = s * scale; }
    float m = fmaxf(l0, l1);
    for (int o = 16; o; o >>= 1) m = fmaxf(m, __shfl_xor_sync(0xffffffffu, m, o));
    float p0 = (n0 < cnt) ? expf(l0 - m) : 0.f;
    float p1 = (n1 < cnt) ? expf(l1 - m) : 0.f;
    float sr0 = (n0 < cnt) ? (g_v[b][n0] - (n0 > 0 ? g_v[b][n0 - 1] : 0.f)) : 0.f;
    float sr1 = (n1 < cnt) ? (g_v[b][n1] - g_v[b][n1 - 1]) : 0.f;
    float Z = p0 + p1, R = p0 * sr0 + p1 * sr1;
    for (int o = 16; o; o >>= 1) { Z += __shfl_xor_sync(0xffffffffu, Z, o); R += __shfl_xor_sync(0xffffffffu, R, o); }
    if (lane == 0) {
        float r = R / Z; rew[b] = r;
        if (1 + b < out_size) out[1 + b] = r;
    }
    __syncthreads();
    if (t == 0) {
        double loss = 0.0;
        for (int i = 0; i < BB / 2; i++) {
            double x = (double)rew[i] - (double)rew[i + BB / 2];   // chosen - reject
            loss += (x > 0.0) ? log1p(exp(-x)) : (-x + log1p(exp(x)));
        }
        out[0] = (float)(loss / (double)(BB / 2));
    }
}

extern "C" void kernel_launch(void* const* d_in, const int* in_sizes, int n_in,
                              void* d_out, int out_size) {
    // Dict (insertion) order for equal sizes: Wq first, then Wk; bq first, then bk.
    const float* hs = 0; const int* mask = 0;
    const float* Wq = 0; const float* Wk = 0; const float* Wr = 0;
    const float* bq = 0; const float* bk = 0; const float* br = 0;
    for (int i = 0; i < n_in; i++) {
        int sz = in_sizes[i];
        const void* p = d_in[i];
        if      (sz == BB * SS * HH) hs   = (const float*)p;
        else if (sz == BB * SS)      mask = (const int*)p;
        else if (sz == HH * DD)      { if (!Wq) Wq = (const float*)p; else Wk = (const float*)p; }
        else if (sz == DD)           { if (!bq) bq = (const float*)p; else bk = (const float*)p; }
        else if (sz == HH)           Wr = (const float*)p;
        else if (sz == 1)            br = (const float*)p;
    }
    float* out = (float*)d_out;

    k_prep<<<BB, 128>>>(mask);
    k_gemv<<<dim3(HC, NT, BB), 256>>>(hs, Wq, Wk, Wr);
    k_rope<<<dim3(NMAX + 1, BB), 64>>>(bq, bk, br);
    k_attn<<<1, 256>>>(out, out_size);
}

// round 15
// speedup vs baseline: 1.0750x; 1.0750x over previous
#include <cuda_runtime.h>
#include <math.h>

#define BB 8
#define SS 4096
#define HH 4096
#define DD 128
#define NMAX 64
#define HC 8              // h chunks
#define HCH (HH/HC)       // 512
#define RT 16             // rows per tile
#define NT2 5             // 4 k-row tiles + 1 q tile

// ---- scratch (no allocations allowed) ----
__device__ int   g_pos[BB][NMAX];
__device__ int   g_cnt[BB];
__device__ int   g_ctr;
__device__ float g_pk[BB][NMAX+1][HC][DD];   // partial k (slots 0..63) / q (slot 64)
__device__ float g_pv[BB][NMAX][HC];         // partial v
__device__ float g_rew[BB];

#define PK2(dst, s)   asm("mov.b64 %0, {%1, %1};" : "=l"(dst) : "f"(s))
#define FMA2(acc, a, b) asm("fma.rn.f32x2 %0, %1, %2, %0;" : "+l"(acc) : "l"(a), "l"(b))
#define UNPK(lo, hi, v) asm("mov.b64 {%0, %1}, %2;" : "=f"(lo), "=f"(hi) : "l"(v))

// Kernel 1: sentence positions via per-warp ballot two-pass (verified).
__global__ void k_prep(const int* __restrict__ mask) {
    int b = blockIdx.x;
    int t = threadIdx.x, w = t >> 5, lane = t & 31;
    if (b == 0 && t == 0) g_ctr = 0;          // reset loss ticket each replay
    const int* mrow = mask + b * SS;
    __shared__ int wcnt[4];
    int cnt = 0;
    for (int it = 0; it < 32; it++) {
        int p = w * 1024 + it * 32 + lane;
        unsigned bal = __ballot_sync(0xffffffffu, mrow[p] > 0);
        cnt += __popc(bal);
    }
    if (lane == 0) wcnt[w] = cnt;
    __syncthreads();
    int base = 0;
    for (int i = 0; i < w; i++) base += wcnt[i];
    int run = base;
    unsigned lmask = (1u << lane) - 1u;
    for (int it = 0; it < 32; it++) {
        int p = w * 1024 + it * 32 + lane;
        bool s = mrow[p] > 0;
        unsigned bal = __ballot_sync(0xffffffffu, s);
        if (s) {
            int r = run + __popc(bal & lmask);
            if (r < NMAX) g_pos[b][r] = p;
        }
        run += __popc(bal);
    }
    if (t == 0) {
        int tot = wcnt[0] + wcnt[1] + wcnt[2] + wcnt[3];
        g_cnt[b] = tot < NMAX ? tot : NMAX;
    }
}

// Kernel 2: gathered GEMV. grid (HC, NT2, B), 256 thr. Block: 16 rows x 512-h chunk.
// Warp w owns rows w and w+8; one float4 W load feeds both rows (f32x2 FMAs).
__global__ void __launch_bounds__(256) k_gemv(const float* __restrict__ hs,
                                              const float* __restrict__ Wq,
                                              const float* __restrict__ Wk,
                                              const float* __restrict__ Wr) {
    int hc = blockIdx.x, tile = blockIdx.y, b = blockIdx.z;
    int t = threadIdx.x, w = t >> 5, lane = t & 31;
    int cnt = g_cnt[b];
    bool qtile = (tile == NT2 - 1);
    if (!qtile && tile * RT >= cnt) return;

    __shared__ __align__(16) float sh[RT][HCH];   // 32 KB
    for (int r = 0; r < RT; r++) {
        int slot = tile * RT + r;
        bool valid = qtile ? (r == 0) : (slot < cnt);
        if (!valid) continue;                     // uniform per r
        int pos = qtile ? g_pos[b][cnt - 1] : g_pos[b][slot];
        const float2* src = (const float2*)(hs + ((size_t)(b * SS + pos)) * HH + (size_t)hc * HCH);
        ((float2*)sh[r])[t] = src[t];             // 256 thr * 2 = 512 floats
    }
    __syncthreads();

    int slot0 = tile * RT + w;
    bool valid0 = qtile ? (w == 0) : (slot0 < cnt);
    if (!valid0) return;
    int slot1 = slot0 + 8;
    bool valid1 = (!qtile) && (slot1 < cnt);

    const float* Wm = qtile ? Wq : Wk;
    const ulonglong2* W2 = (const ulonglong2*)(Wm + (size_t)hc * HCH * DD) + lane;
    const float* hr0 = sh[w];
    const float* hr1 = sh[w + 8];

    unsigned long long a01_0 = 0ull, a23_0 = 0ull, a01_1 = 0ull, a23_1 = 0ull;
#pragma unroll 8
    for (int h = 0; h < HCH; h++) {
        ulonglong2 wv = W2[(size_t)h * 32];
        float hv0 = hr0[h];
        unsigned long long h2; PK2(h2, hv0);
        FMA2(a01_0, h2, wv.x);
        FMA2(a23_0, h2, wv.y);
        float hv1 = hr1[h];
        unsigned long long h3; PK2(h3, hv1);
        FMA2(a01_1, h3, wv.x);
        FMA2(a23_1, h3, wv.y);
    }
    int outslot0 = qtile ? NMAX : slot0;
    {
        float4 o; UNPK(o.x, o.y, a01_0); UNPK(o.z, o.w, a23_0);
        ((float4*)g_pk[b][outslot0][hc])[lane] = o;
    }
    if (valid1) {
        float4 o; UNPK(o.x, o.y, a01_1); UNPK(o.z, o.w, a23_1);
        ((float4*)g_pk[b][slot1][hc])[lane] = o;
    }

    if (!qtile) {
        const float* wr = Wr + hc * HCH;
        float va0 = 0.f, va1 = 0.f;
        for (int h = lane; h < HCH; h += 32) {
            float wv = wr[h];
            va0 = fmaf(hr0[h], wv, va0);
            va1 = fmaf(hr1[h], wv, va1);
        }
        for (int o = 16; o; o >>= 1) {
            va0 += __shfl_xor_sync(0xffffffffu, va0, o);
            va1 += __shfl_xor_sync(0xffffffffu, va1, o);
        }
        if (lane == 0) {
            g_pv[b][slot0][hc] = va0;
            if (valid1) g_pv[b][slot1][hc] = va1;
        }
    }
}

// Kernel 3: fused reduce + bias + RoPE + attention + reward + loss.
// grid BB blocks, 128 threads; loss by the last-finishing block (atomic ticket).
__global__ void __launch_bounds__(128) k_tail(const float* __restrict__ bq,
                                              const float* __restrict__ bk,
                                              const float* __restrict__ br,
                                              float* __restrict__ out, int out_size) {
    int b = blockIdx.x, t = threadIdx.x;
    int cnt = g_cnt[b];
    __shared__ float sk[NMAX][129];    // padded: conflict-free column reads
    __shared__ float sq[DD];
    __shared__ float sv[NMAX];

    // reduce partials + rope, one slot per iteration (no syncs -> cross-iter ILP)
    for (int s = 0; s <= cnt; s++) {
        bool qs = (s == cnt);
        int srcslot = qs ? NMAX : s;
        float a = 0.f;
#pragma unroll
        for (int c = 0; c < HC; c++) a += g_pk[b][srcslot][c][t];
        a += qs ? bq[t] : bk[t];
        int n = qs ? (cnt - 1) : s;
        float partner = __shfl_xor_sync(0xffffffffu, a, 1);
        int j = t >> 1;
        float freq = expf(-(float)j * 0.14391156831212787f);  // 10000^(-j/64)
        float ang = (float)n * freq;
        float sn, cs; sincosf(ang, &sn, &cs);
        float r = (t & 1) ? (partner * sn + a * cs) : (a * cs - partner * sn);
        if (qs) sq[t] = r; else sk[s][t] = r;
        if (!qs && t == 0) {
            float v = br[0];
#pragma unroll
            for (int c = 0; c < HC; c++) v += g_pv[b][s][c];
            sv[s] = v;
        }
    }
    __syncthreads();

    if (t < 32) {
        int lane = t;
        const float scale = 0.08838834764831845f; // 1/sqrt(128)
        int n0 = lane, n1 = lane + 32;
        float l0 = -INFINITY, l1 = -INFINITY;
        if (n0 < cnt) { float s = 0.f; for (int d = 0; d < DD; d++) s = fmaf(sq[d], sk[n0][d], s); l0 = s * scale; }
        if (n1 < cnt) { float s = 0.f; for (int d = 0; d < DD; d++) s = fmaf(sq[d], sk[n1][d], s); l1 = s * scale; }
        float m = fmaxf(l0, l1);
        for (int o = 16; o; o >>= 1) m = fmaxf(m, __shfl_xor_sync(0xffffffffu, m, o));
        float p0 = (n0 < cnt) ? expf(l0 - m) : 0.f;
        float p1 = (n1 < cnt) ? expf(l1 - m) : 0.f;
        float sr0 = (n0 < cnt) ? (sv[n0] - (n0 > 0 ? sv[n0 - 1] : 0.f)) : 0.f;
        float sr1 = (n1 < cnt) ? (sv[n1] - sv[n1 - 1]) : 0.f;
        float Z = p0 + p1, R = p0 * sr0 + p1 * sr1;
        for (int o = 16; o; o >>= 1) { Z += __shfl_xor_sync(0xffffffffu, Z, o); R += __shfl_xor_sync(0xffffffffu, R, o); }
        if (lane == 0) {
            float r = R / Z;
            g_rew[b] = r;
            if (1 + b < out_size) out[1 + b] = r;
            __threadfence();
            int old = atomicAdd(&g_ctr, 1);
            if (old == BB - 1) {
                __threadfence();
                double loss = 0.0;
                for (int i = 0; i < BB / 2; i++) {
                    double x = (double)g_rew[i] - (double)g_rew[i + BB / 2];
                    loss += (x > 0.0) ? log1p(exp(-x)) : (-x + log1p(exp(x)));
                }
                out[0] = (float)(loss / (double)(BB / 2));
            }
        }
    }
}

extern "C" void kernel_launch(void* const* d_in, const int* in_sizes, int n_in,
                              void* d_out, int out_size) {
    // Dict (insertion) order for equal sizes: Wq first, then Wk; bq first, then bk.
    const float* hs = 0; const int* mask = 0;
    const float* Wq = 0; const float* Wk = 0; const float* Wr = 0;
    const float* bq = 0; const float* bk = 0; const float* br = 0;
    for (int i = 0; i < n_in; i++) {
        int sz = in_sizes[i];
        const void* p = d_in[i];
        if      (sz == BB * SS * HH) hs   = (const float*)p;
        else if (sz == BB * SS)      mask = (const int*)p;
        else if (sz == HH * DD)      { if (!Wq) Wq = (const float*)p; else Wk = (const float*)p; }
        else if (sz == DD)           { if (!bq) bq = (const float*)p; else bk = (const float*)p; }
        else if (sz == HH)           Wr = (const float*)p;
        else if (sz == 1)            br = (const float*)p;
    }
    float* out = (float*)d_out;

    k_prep<<<BB, 128>>>(mask);
    k_gemv<<<dim3(HC, NT2, BB), 256>>>(hs, Wq, Wk, Wr);
    k_tail<<<BB, 128>>>(bq, bk, br, out, out_size);
}

// round 16
// speedup vs baseline: 1.4778x; 1.3748x over previous
#include <cuda_runtime.h>
#include <math.h>

#define BB 8
#define SS 4096
#define HH 4096
#define DD 128
#define NMAX 64
#define HC 16             // h chunks
#define HCH (HH/HC)       // 256 -> W chunk = 128 KB, fits L1
#define RPB 32            // k rows per block
#define KT 2              // k tiles (covers 64 slots)

// ---- scratch (no allocations allowed) ----
__device__ int   g_pos[BB][NMAX];
__device__ int   g_cnt[BB];
__device__ int   g_ctr;
__device__ float g_pk[BB][NMAX+1][HC][DD];   // partial k (0..63) / q (64)
__device__ float g_pv[BB][NMAX][HC];
__device__ float g_rew[BB];

#define PK2(dst, s)     asm("mov.b64 %0, {%1, %1};" : "=l"(dst) : "f"(s))
#define FMA2(acc, a, b) asm("fma.rn.f32x2 %0, %1, %2, %0;" : "+l"(acc) : "l"(a), "l"(b))
#define UNPK(lo, hi, v) asm("mov.b64 {%0, %1}, %2;" : "=f"(lo), "=f"(hi) : "l"(v))

// K1: positions. All 32 loads per lane issued up-front (MLP=32), ballots from regs.
__global__ void k_prep(const int* __restrict__ mask) {
    int b = blockIdx.x, t = threadIdx.x, w = t >> 5, lane = t & 31;
    if (b == 0 && t == 0) g_ctr = 0;
    const int* mrow = mask + b * SS + w * 1024;
    int v[32];
#pragma unroll
    for (int j = 0; j < 32; j++) v[j] = mrow[j * 32 + lane];
    unsigned bals[32]; int cnt = 0;
#pragma unroll
    for (int j = 0; j < 32; j++) { bals[j] = __ballot_sync(0xffffffffu, v[j] > 0); cnt += __popc(bals[j]); }
    __shared__ int wcnt[4];
    if (lane == 0) wcnt[w] = cnt;
    __syncthreads();
    int run = 0;
    for (int i = 0; i < w; i++) run += wcnt[i];
    unsigned lm = (1u << lane) - 1u;
#pragma unroll
    for (int j = 0; j < 32; j++) {
        if (v[j] > 0) {
            int r = run + __popc(bals[j] & lm);
            if (r < NMAX) g_pos[b][r] = w * 1024 + j * 32 + lane;
        }
        run += __popc(bals[j]);
    }
    if (t == 0) {
        int tot = wcnt[0] + wcnt[1] + wcnt[2] + wcnt[3];
        g_cnt[b] = tot < NMAX ? tot : NMAX;
    }
}

// K2: gathered GEMV. grid (HC, KT+1, B), 256 thr.
// k tiles: 32 rows/block, warp w owns rows w*4..w*4+3 (one W load feeds 4 rows).
// q tile: warp 0 computes the single q row.
__global__ void __launch_bounds__(256) k_gemv(const float* __restrict__ hs,
                                              const float* __restrict__ Wq,
                                              const float* __restrict__ Wk,
                                              const float* __restrict__ Wr) {
    int hc = blockIdx.x, tile = blockIdx.y, b = blockIdx.z;
    int t = threadIdx.x, w = t >> 5, lane = t & 31;
    int cnt = g_cnt[b];
    bool qtile = (tile == KT);
    if (!qtile && tile * RPB >= cnt) return;

    __shared__ __align__(16) float sh[RPB][HCH];   // 32 KB

    if (qtile) {
        int pos = g_pos[b][cnt - 1];
        sh[0][t] = hs[((size_t)(b * SS + pos)) * HH + (size_t)hc * HCH + t];  // 256 thr = HCH
        __syncthreads();
        if (w != 0) return;
        const ulonglong2* W2 = (const ulonglong2*)(Wq + (size_t)hc * HCH * DD) + lane;
        unsigned long long a01 = 0ull, a23 = 0ull;
#pragma unroll 8
        for (int h = 0; h < HCH; h++) {
            ulonglong2 wv = W2[(size_t)h * 32];
            unsigned long long h2; PK2(h2, sh[0][h]);
            FMA2(a01, h2, wv.x);
            FMA2(a23, h2, wv.y);
        }
        float4 o; UNPK(o.x, o.y, a01); UNPK(o.z, o.w, a23);
        ((float4*)g_pk[b][NMAX][hc])[lane] = o;
        return;
    }

    // stage up to 32 rows; warp w stages rows w, w+8, w+16, w+24
#pragma unroll
    for (int rr = 0; rr < 4; rr++) {
        int r = w + rr * 8;
        int slot = tile * RPB + r;
        if (slot < cnt) {
            int pos = g_pos[b][slot];
            const float4* src = (const float4*)(hs + ((size_t)(b * SS + pos)) * HH + (size_t)hc * HCH);
            ((float4*)sh[r])[lane] = src[lane];
            ((float4*)sh[r])[lane + 32] = src[lane + 32];
        }
    }
    __syncthreads();

    int base = tile * RPB + w * 4;
    if (base >= cnt) return;
    int lr = w * 4;

    const ulonglong2* W2 = (const ulonglong2*)(Wk + (size_t)hc * HCH * DD) + lane;
    unsigned long long a01[4] = {0,0,0,0}, a23[4] = {0,0,0,0};
#pragma unroll 2
    for (int h = 0; h < HCH; h += 4) {
        float4 hv[4];
#pragma unroll
        for (int r = 0; r < 4; r++) hv[r] = *(const float4*)&sh[lr + r][h];
#pragma unroll
        for (int hh = 0; hh < 4; hh++) {
            ulonglong2 wv = W2[(size_t)(h + hh) * 32];
#pragma unroll
            for (int r = 0; r < 4; r++) {
                unsigned long long h2; PK2(h2, ((const float*)&hv[r])[hh]);
                FMA2(a01[r], h2, wv.x);
                FMA2(a23[r], h2, wv.y);
            }
        }
    }
#pragma unroll
    for (int r = 0; r < 4; r++) {
        if (base + r < cnt) {
            float4 o; UNPK(o.x, o.y, a01[r]); UNPK(o.z, o.w, a23[r]);
            ((float4*)g_pk[b][base + r][hc])[lane] = o;
        }
    }

    // v partials for this warp's 4 rows
    const float* wr = Wr + hc * HCH;
    float va[4] = {0.f, 0.f, 0.f, 0.f};
#pragma unroll
    for (int h0 = 0; h0 < HCH; h0 += 32) {
        int h = h0 + lane;
        float wv = wr[h];
#pragma unroll
        for (int r = 0; r < 4; r++) va[r] = fmaf(sh[lr + r][h], wv, va[r]);
    }
#pragma unroll
    for (int r = 0; r < 4; r++) {
        float v = va[r];
        for (int o = 16; o; o >>= 1) v += __shfl_xor_sync(0xffffffffu, v, o);
        if (lane == 0 && base + r < cnt) g_pv[b][base + r][hc] = v;
    }
}

// K3: fused reduce + bias + RoPE + attention + reward + loss. BB blocks x 512 thr.
// Slots striped over 4 thread-groups for MLP; loss via atomic ticket (reset in k_prep).
__global__ void __launch_bounds__(512) k_tail(const float* __restrict__ bq,
                                              const float* __restrict__ bk,
                                              const float* __restrict__ br,
                                              float* __restrict__ out, int out_size) {
    int b = blockIdx.x, t = threadIdx.x;
    int sg = t >> 7, td = t & 127;
    int cnt = g_cnt[b];
    __shared__ float sk[NMAX][129];
    __shared__ float sq[DD];
    __shared__ float sv[NMAX];

    float freq = expf(-(float)(td >> 1) * 0.14391156831212787f);  // 10000^(-j/64)
    for (int s = sg; s <= cnt; s += 4) {
        bool qs = (s == cnt);
        int srcslot = qs ? NMAX : s;
        float a = 0.f;
#pragma unroll
        for (int c = 0; c < HC; c++) a += g_pk[b][srcslot][c][td];
        a += qs ? bq[td] : bk[td];
        int n = qs ? (cnt - 1) : s;
        float partner = __shfl_xor_sync(0xffffffffu, a, 1);
        float sn, cs; __sincosf((float)n * freq, &sn, &cs);
        float r = (td & 1) ? (partner * sn + a * cs) : (a * cs - partner * sn);
        if (qs) sq[td] = r; else sk[s][td] = r;
        if (!qs && td == 0) {
            float v = br[0];
#pragma unroll
            for (int c = 0; c < HC; c++) v += g_pv[b][s][c];
            sv[s] = v;
        }
    }
    __syncthreads();

    if (t < 32) {
        int lane = t;
        const float scale = 0.08838834764831845f; // 1/sqrt(128)
        int n0 = lane, n1 = lane + 32;
        float l0 = -INFINITY, l1 = -INFINITY;
        if (n0 < cnt) { float s = 0.f; for (int d = 0; d < DD; d++) s = fmaf(sq[d], sk[n0][d], s); l0 = s * scale; }
        if (n1 < cnt) { float s = 0.f; for (int d = 0; d < DD; d++) s = fmaf(sq[d], sk[n1][d], s); l1 = s * scale; }
        float m = fmaxf(l0, l1);
        for (int o = 16; o; o >>= 1) m = fmaxf(m, __shfl_xor_sync(0xffffffffu, m, o));
        float p0 = (n0 < cnt) ? __expf(l0 - m) : 0.f;
        float p1 = (n1 < cnt) ? __expf(l1 - m) : 0.f;
        float sr0 = (n0 < cnt) ? (sv[n0] - (n0 > 0 ? sv[n0 - 1] : 0.f)) : 0.f;
        float sr1 = (n1 < cnt) ? (sv[n1] - sv[n1 - 1]) : 0.f;
        float Z = p0 + p1, R = p0 * sr0 + p1 * sr1;
        for (int o = 16; o; o >>= 1) { Z += __shfl_xor_sync(0xffffffffu, Z, o); R += __shfl_xor_sync(0xffffffffu, R, o); }
        if (lane == 0) {
            float r = R / Z;
            g_rew[b] = r;
            if (1 + b < out_size) out[1 + b] = r;
            __threadfence();
            int old = atomicAdd(&g_ctr, 1);
            if (old == BB - 1) {
                __threadfence();
                double loss = 0.0;
                for (int i = 0; i < BB / 2; i++) {
                    double x = (double)g_rew[i] - (double)g_rew[i + BB / 2];
                    loss += (x > 0.0) ? log1p(exp(-x)) : (-x + log1p(exp(x)));
                }
                out[0] = (float)(loss / (double)(BB / 2));
            }
        }
    }
}

extern "C" void kernel_launch(void* const* d_in, const int* in_sizes, int n_in,
                              void* d_out, int out_size) {
    // Dict (insertion) order for equal sizes: Wq first, then Wk; bq first, then bk.
    const float* hs = 0; const int* mask = 0;
    const float* Wq = 0; const float* Wk = 0; const float* Wr = 0;
    const float* bq = 0; const float* bk = 0; const float* br = 0;
    for (int i = 0; i < n_in; i++) {
        int sz = in_sizes[i];
        const void* p = d_in[i];
        if      (sz == BB * SS * HH) hs   = (const float*)p;
        else if (sz == BB * SS)      mask = (const int*)p;
        else if (sz == HH * DD)      { if (!Wq) Wq = (const float*)p; else Wk = (const float*)p; }
        else if (sz == DD)           { if (!bq) bq = (const float*)p; else bk = (const float*)p; }
        else if (sz == HH)           Wr = (const float*)p;
        else if (sz == 1)            br = (const float*)p;
    }
    float* out = (float*)d_out;

    k_prep<<<BB, 128>>>(mask);
    k_gemv<<<dim3(HC, KT + 1, BB), 256>>>(hs, Wq, Wk, Wr);
    k_tail<<<BB, 512>>>(bq, bk, br, out, out_size);
}